// round 5
// baseline (speedup 1.0000x reference)
#include <cuda_runtime.h>
#include <math.h>

#define HW 65536            // 256*256
#define BATCH 2
#define NPIX (BATCH*HW)     // 131072
#define NW 1024
#define KEEP 512

typedef unsigned long long u64;
typedef unsigned int u32;

// ---------------- packed f32x2 helpers ----------------
__device__ __forceinline__ u64 fma2(u64 a, u64 b, u64 c) {
    u64 d; asm("fma.rn.f32x2 %0,%1,%2,%3;" : "=l"(d) : "l"(a), "l"(b), "l"(c)); return d;
}
__device__ __forceinline__ u64 mul2(u64 a, u64 b) {
    u64 d; asm("mul.rn.f32x2 %0,%1,%2;" : "=l"(d) : "l"(a), "l"(b)); return d;
}
__device__ __forceinline__ u64 add2(u64 a, u64 b) {
    u64 d; asm("add.rn.f32x2 %0,%1,%2;" : "=l"(d) : "l"(a), "l"(b)); return d;
}
__device__ __forceinline__ u64 pack2(float lo, float hi) {
    u64 r; asm("mov.b64 %0,{%1,%2};" : "=l"(r) : "f"(lo), "f"(hi)); return r;
}
__device__ __forceinline__ float hadd2(u64 v) {
    float lo, hi; asm("mov.b64 {%0,%1},%2;" : "=f"(lo), "=f"(hi) : "l"(v)); return lo + hi;
}
__device__ __forceinline__ float lo2(u64 v) {
    float lo, hi; asm("mov.b64 {%0,%1},%2;" : "=f"(lo), "=f"(hi) : "l"(v)); return lo;
}
__device__ __forceinline__ float hi2(u64 v) {
    float lo, hi; asm("mov.b64 {%0,%1},%2;" : "=f"(lo), "=f"(hi) : "l"(v)); return hi;
}

// ---------------- tf32 helpers ----------------
__device__ __forceinline__ void tf32split(float x, u32& h, u32& l) {
    asm("cvt.rna.tf32.f32 %0,%1;" : "=r"(h) : "f"(x));
    float r = x - __uint_as_float(h);
    asm("cvt.rna.tf32.f32 %0,%1;" : "=r"(l) : "f"(r));
}
__device__ __forceinline__ void mma8(float* d, const u32* a, const u32* b) {
    asm volatile("mma.sync.aligned.m16n8k8.row.col.f32.tf32.tf32.f32 "
        "{%0,%1,%2,%3},{%4,%5,%6,%7},{%8,%9},{%0,%1,%2,%3};"
        : "+f"(d[0]), "+f"(d[1]), "+f"(d[2]), "+f"(d[3])
        : "r"(a[0]), "r"(a[1]), "r"(a[2]), "r"(a[3]), "r"(b[0]), "r"(b[1]));
}

// ---------------- scratch ----------------
__device__ float g_q[NPIX*64];     // NHWC
__device__ float g_k[NPIX*64];
__device__ float g_v[NPIX*64];
__device__ float g_mix[NPIX*64];
__device__ float g_h1p[17*NPIX];   // planar
__device__ float g_sa[NPIX];
__device__ float g_xm[NPIX];
__device__ float g_score[BATCH*NW];
__device__ int   g_hard[BATCH*KEEP];
__device__ int   g_ishard[BATCH*NW];

// ======================= K1: qkv via tf32 mma (3x split) =======================
#define QKV_SMEM ((64*136*2 + 192*68*2) * 4)
__global__ __launch_bounds__(256) void k_qkv(
    const float* __restrict__ x,
    const float* __restrict__ Wq, const float* __restrict__ bq,
    const float* __restrict__ Wk, const float* __restrict__ bk,
    const float* __restrict__ Wv, const float* __restrict__ bv)
{
    extern __shared__ __align__(16) u32 sm[];
    u32* sAh = sm;                    // [64][136]
    u32* sAl = sAh + 64*136;
    u32* sBh = sAl + 64*136;          // [192][68]
    u32* sBl = sBh + 192*68;
    float* sC = (float*)sm;           // [128][196]

    int t = threadIdx.x;
    int p0 = blockIdx.x * 128;
    int b  = p0 >> 16, p = p0 & (HW - 1);
    const float* xb = x + (size_t)b * 64 * HW + p;

#pragma unroll
    for (int i = 0; i < 8; i++) {
        int fidx = i * 256 + t;
        int ic = fidx >> 5, px4 = (fidx & 31) << 2;
        float4 v = *(const float4*)(xb + (size_t)ic * HW + px4);
        uint4 h, l;
        tf32split(v.x, h.x, l.x); tf32split(v.y, h.y, l.y);
        tf32split(v.z, h.z, l.z); tf32split(v.w, h.w, l.w);
        *(uint4*)(sAh + ic * 136 + px4) = h;
        *(uint4*)(sAl + ic * 136 + px4) = l;
    }
#pragma unroll
    for (int i = 0; i < 12; i++) {
        int widx = i * 256 + t;
        int oc = widx >> 4, ic4 = (widx & 15) << 2;
        const float* Wm = (oc < 64) ? Wq : (oc < 128) ? Wk : Wv;
        float4 v = *(const float4*)(Wm + (oc & 63) * 64 + ic4);
        uint4 h, l;
        tf32split(v.x, h.x, l.x); tf32split(v.y, h.y, l.y);
        tf32split(v.z, h.z, l.z); tf32split(v.w, h.w, l.w);
        *(uint4*)(sBh + oc * 68 + ic4) = h;
        *(uint4*)(sBl + oc * 68 + ic4) = l;
    }
    __syncthreads();

    int lane = t & 31, warp = t >> 5;
    int g = lane >> 2, i4 = lane & 3;
    int mg = warp >> 2, ng = warp & 3;

    float acc[4][6][4];
#pragma unroll
    for (int mt = 0; mt < 4; mt++)
#pragma unroll
        for (int nt = 0; nt < 6; nt++)
#pragma unroll
            for (int c = 0; c < 4; c++) acc[mt][nt][c] = 0.f;

#pragma unroll
    for (int kt = 0; kt < 8; kt++) {
        u32 ah[4][4], al[4][4];
#pragma unroll
        for (int mt = 0; mt < 4; mt++) {
            int mrow = mg * 64 + mt * 16 + g;
            const u32* pA = sAh + (kt * 8 + i4) * 136 + mrow;
            const u32* qA = sAl + (kt * 8 + i4) * 136 + mrow;
            ah[mt][0] = pA[0]; ah[mt][1] = pA[8]; ah[mt][2] = pA[4*136]; ah[mt][3] = pA[4*136+8];
            al[mt][0] = qA[0]; al[mt][1] = qA[8]; al[mt][2] = qA[4*136]; al[mt][3] = qA[4*136+8];
        }
        u32 bh[6][2], bl[6][2];
#pragma unroll
        for (int nt = 0; nt < 6; nt++) {
            int ocol = ng * 48 + nt * 8 + g;
            const u32* pB = sBh + ocol * 68 + kt * 8 + i4;
            const u32* qB = sBl + ocol * 68 + kt * 8 + i4;
            bh[nt][0] = pB[0]; bh[nt][1] = pB[4];
            bl[nt][0] = qB[0]; bl[nt][1] = qB[4];
        }
#pragma unroll
        for (int mt = 0; mt < 4; mt++)
#pragma unroll
            for (int nt = 0; nt < 6; nt++) {
                mma8(acc[mt][nt], ah[mt], bh[nt]);
                mma8(acc[mt][nt], ah[mt], bl[nt]);
                mma8(acc[mt][nt], al[mt], bh[nt]);
            }
    }
    __syncthreads();

#pragma unroll
    for (int mt = 0; mt < 4; mt++)
#pragma unroll
        for (int nt = 0; nt < 6; nt++) {
            int row = mg * 64 + mt * 16 + g;
            int col = ng * 48 + nt * 8 + 2 * i4;
            float* c = sC + row * 196 + col;
            c[0] = acc[mt][nt][0]; c[1] = acc[mt][nt][1];
            c += 8 * 196;
            c[0] = acc[mt][nt][2]; c[1] = acc[mt][nt][3];
        }
    __syncthreads();

#pragma unroll
    for (int i = 0; i < 24; i++) {
        int fidx = i * 256 + t;
        int mat = fidx >> 11;
        int r = fidx & 2047;
        int px = r >> 4, c4 = (r & 15) << 2;
        float4 v = *(float4*)(sC + px * 196 + mat * 64 + c4);
        const float* bias = (mat == 0) ? bq : (mat == 1) ? bk : bv;
        float4 bv4 = *(const float4*)(bias + c4);
        v.x += bv4.x; v.y += bv4.y; v.z += bv4.z; v.w += bv4.w;
        float* gX = (mat == 0) ? g_q : (mat == 1) ? g_k : g_v;
        *(float4*)(gX + (size_t)(p0 + px) * 64 + c4) = v;
    }
}

// ======================= K2: pin conv + LN + lrelu + xm =======================
__global__ __launch_bounds__(128) void k_pin(
    const float* __restrict__ cg,
    const float* __restrict__ pinW, const float* __restrict__ pinb,
    const float* __restrict__ lnw,  const float* __restrict__ lnb)
{
    __shared__ float vt[128][66];
    __shared__ u64 sw2[17*34];
    __shared__ float sb[17], slw[17], slb[17];

    int t = threadIdx.x;
    int p0 = blockIdx.x * 128;

    const u64* pw64 = (const u64*)pinW;
    for (int i = t; i < 17*34; i += 128) sw2[i] = pw64[i];
    if (t < 17) { sb[t] = pinb[t]; slw[t] = lnw[t]; slb[t] = lnb[t]; }

#pragma unroll
    for (int i = 0; i < 16; i++) {
        int fidx = i * 128 + t;
        int row = fidx >> 4, c4 = fidx & 15;
        float4 v = *(const float4*)(g_v + (size_t)(p0 + row) * 64 + 4 * c4);
        vt[row][4*c4+0] = v.x; vt[row][4*c4+1] = v.y;
        vt[row][4*c4+2] = v.z; vt[row][4*c4+3] = v.w;
    }
    __syncthreads();

    int g = p0 + t;
    int b = g >> 16, p = g & (HW - 1);
    int y = p >> 8, xx = p & 255;

    u64 c2[34];
    const u64* vrow = (const u64*)&vt[t][0];
#pragma unroll
    for (int i = 0; i < 32; i++) c2[i] = vrow[i];
    c2[32] = pack2(cg[(size_t)b * 2 * HW + p], cg[(size_t)b * 2 * HW + HW + p]);
    c2[33] = pack2(-1.0f + (2.0f / 7.0f) * (float)(y & 7),
                   -1.0f + (2.0f / 7.0f) * (float)(xx & 7));

    float h[17];
    for (int oc = 0; oc < 17; oc++) {
        const u64* w = &sw2[oc * 34];
        u64 a0 = 0, a1 = 0;
#pragma unroll
        for (int i = 0; i < 34; i += 2) {
            a0 = fma2(c2[i],   w[i],   a0);
            a1 = fma2(c2[i+1], w[i+1], a1);
        }
        h[oc] = sb[oc] + hadd2(a0) + hadd2(a1);
    }
    float u = 0.f;
#pragma unroll
    for (int oc = 0; oc < 17; oc++) u += h[oc];
    u *= (1.0f / 17.0f);
    float sv = 0.f;
#pragma unroll
    for (int oc = 0; oc < 17; oc++) { float d = h[oc] - u; sv += d * d; }
    sv *= (1.0f / 17.0f);
    float inv = rsqrtf(sv + 1e-6f);

    float xs = 0.f;
#pragma unroll
    for (int oc = 0; oc < 17; oc++) {
        float tv = slw[oc] * (h[oc] - u) * inv + slb[oc];
        tv = (tv >= 0.f) ? tv : 0.1f * tv;
        g_h1p[(size_t)oc * NPIX + g] = tv;
        xs += tv;
    }
    g_xm[g] = xs * (1.0f / 17.0f);
}

// ======================= K3: 3x3 conv (17->1) + sigmoid =======================
__global__ __launch_bounds__(256) void k_sa(
    const float* __restrict__ saW, const float* __restrict__ sab)
{
    __shared__ float swt[153];
    for (int i = threadIdx.x; i < 153; i += 256) swt[i] = saW[i];
    __syncthreads();
    int g = blockIdx.x * 256 + threadIdx.x;
    int b = g >> 16, p = g & (HW - 1);
    int y = p >> 8, x = p & 255;
    float acc = sab[0];
#pragma unroll
    for (int c = 0; c < 17; c++) {
        const float* plane = g_h1p + (size_t)c * NPIX + (size_t)b * HW;
        const float* wr = &swt[c * 9];
#pragma unroll
        for (int dy = -1; dy <= 1; dy++) {
            int yy = y + dy;
            if ((unsigned)yy > 255u) continue;
#pragma unroll
            for (int dx = -1; dx <= 1; dx++) {
                int xxp = x + dx;
                if ((unsigned)xxp > 255u) continue;
                acc += plane[yy * 256 + xxp] * wr[(dy + 1) * 3 + (dx + 1)];
            }
        }
    }
    g_sa[g] = 1.0f / (1.0f + __expf(-acc));
}

// ======================= K4: window score, warp-per-window =======================
__global__ __launch_bounds__(256) void k_score(
    const float* __restrict__ m1W, const float* __restrict__ m1b,
    const float* __restrict__ m2W, const float* __restrict__ m2b)
{
    int t = threadIdx.x, lane = t & 31, warp = t >> 5;
    int gw = blockIdx.x * 8 + warp;
    int b = gw >> 10, w = gw & (NW - 1);
    int wy = w >> 5, wx = w & 31;
    int qy = lane >> 2, qx2 = (lane & 3) * 2;
    int tok = qy * 8 + qx2;

    u64 xv = *(const u64*)(g_xm + b * HW + (wy * 8 + qy) * 256 + wx * 8 + qx2);
    u64 pj[4];
#pragma unroll
    for (int j2 = 0; j2 < 4; j2++) {
        u64 w0 = *(const u64*)(m1W + (2*j2) * 64 + tok);
        u64 w1 = *(const u64*)(m1W + (2*j2+1) * 64 + tok);
        pj[j2] = pack2(hadd2(mul2(xv, w0)), hadd2(mul2(xv, w1)));
    }
#pragma unroll
    for (int s = 16; s > 0; s >>= 1) {
#pragma unroll
        for (int j2 = 0; j2 < 4; j2++)
            pj[j2] = add2(pj[j2], __shfl_xor_sync(0xffffffffu, pj[j2], s));
    }
    if (lane == 0) {
        float z[8];
#pragma unroll
        for (int j2 = 0; j2 < 4; j2++) { z[2*j2] = lo2(pj[j2]); z[2*j2+1] = hi2(pj[j2]); }
        float l0 = m2b[0], l1 = m2b[1];
#pragma unroll
        for (int j = 0; j < 8; j++) {
            float a = z[j] + m1b[j];
            a = (a >= 0.f) ? a : 0.1f * a;
            l0 += a * m2W[j]; l1 += a * m2W[8 + j];
        }
        g_score[gw] = 1.0f / (1.0f + __expf(l1 - l0));
    }
}

// ======================= K5: deterministic rank -> top-512 =======================
__global__ __launch_bounds__(1024) void k_rank()
{
    __shared__ float s[NW];
    int b = blockIdx.x;
    int i = threadIdx.x;
    s[i] = g_score[b * NW + i];
    __syncthreads();
    float si = s[i];
    int r = 0;
    for (int j = 0; j < NW; j++) {
        float sj = s[j];
        r += (sj > si) || (sj == si && j < i);
    }
    if (r < KEEP) {
        g_hard[b * KEEP + r] = i;
        g_ishard[b * NW + i] = 1;
    } else {
        g_ishard[b * NW + i] = 0;
    }
}

// ======================= K6: attention, single pass (no max-sub), LDS.128 =======================
#define ATTN_SMEM (144*64*4*2 + 64*68*4 + 184*8*2)
__global__ __launch_bounds__(256) void k_attn(
    const float* __restrict__ relh, const float* __restrict__ relw)
{
    extern __shared__ __align__(16) char dyn[];
    float* ks = (float*)dyn;                 // K pre-scaled by 0.25
    float* vs = ks + 144*64;
    float* qs = vs + 144*64;                 // [64][68]
    u64* srw  = (u64*)(qs + 64*68);
    u64* srh  = srw + 184;

    int t = threadIdx.x;
    int head = t >> 6, tok = t & 63;
    int b = blockIdx.x >> 9;
    int w = g_hard[blockIdx.x];
    int wy = w >> 5, wx = w & 31;

    u64 s2 = pack2(0.25f, 0.25f);
    const u64* rw64 = (const u64*)relw;
    const u64* rh64 = (const u64*)relh;
    for (int i = t; i < 184; i += 256) {
        srw[i] = mul2(rw64[i], s2);
        srh[i] = mul2(rh64[i], s2);
    }

    int y0 = wy * 8 - 2, x0 = wx * 8 - 2;
#pragma unroll
    for (int i = 0; i < 9; i++) {
        int fidx = i * 256 + t;
        int kk = fidx >> 4, c4 = fidx & 15;
        int yy = y0 + kk / 12, xxp = x0 + kk % 12;
        float4 kv = make_float4(0.f, 0.f, 0.f, 0.f), vv = kv;
        if ((unsigned)yy < 256u && (unsigned)xxp < 256u) {
            size_t base = ((size_t)(b * HW + yy * 256 + xxp)) * 64 + 4 * c4;
            kv = *(const float4*)(g_k + base);
            vv = *(const float4*)(g_v + base);
            kv.x *= 0.25f; kv.y *= 0.25f; kv.z *= 0.25f; kv.w *= 0.25f;
        }
        *(float4*)(ks + kk * 64 + 4 * c4) = kv;
        *(float4*)(vs + kk * 64 + 4 * c4) = vv;
    }
#pragma unroll
    for (int i = 0; i < 4; i++) {
        int fidx = i * 256 + t;
        int tk = fidx >> 4, c4 = fidx & 15;
        int py = wy * 8 + (tk >> 3), px = wx * 8 + (tk & 7);
        float4 qv = *(const float4*)(g_q + ((size_t)(b * HW + py * 256 + px)) * 64 + 4 * c4);
        *(float4*)(qs + tk * 68 + 4 * c4) = qv;
    }
    __syncthreads();

    // q into regs (16B-aligned: 68*4*tok is multiple of 16, head*64B)
    u64 q2[8];
    {
        const ulonglong2* qrow = (const ulonglong2*)(qs + tok * 68 + head * 16);
#pragma unroll
        for (int i = 0; i < 4; i++) {
            ulonglong2 v = qrow[i];
            q2[2*i] = v.x; q2[2*i+1] = v.y;
        }
    }

    int qy = tok >> 3, qx = tok & 7;

    // per-column / per-row relative bias (already scaled)
    float rwv[12], rhv[12];
#pragma unroll
    for (int k2 = 0; k2 < 12; k2++) {
        const ulonglong2* pw = (const ulonglong2*)&srw[(k2 - qx + 11) * 8];
        const ulonglong2* ph = (const ulonglong2*)&srh[(k2 - qy + 11) * 8];
        u64 a0 = 0, a1 = 0, c0 = 0, c1 = 0;
#pragma unroll
        for (int i = 0; i < 4; i++) {
            ulonglong2 wv = pw[i], hv = ph[i];
            a0 = fma2(q2[2*i],   wv.x, a0);
            a1 = fma2(q2[2*i+1], wv.y, a1);
            c0 = fma2(q2[2*i],   hv.x, c0);
            c1 = fma2(q2[2*i+1], hv.y, c1);
        }
        rwv[k2] = hadd2(a0) + hadd2(a1);
        rhv[k2] = hadd2(c0) + hadd2(c1);
    }

    // single pass: exp (no max subtraction -- logits are small), accumulate V
    float sum = 0.f;
    u64 acc[8] = {0,0,0,0,0,0,0,0};
    for (int ky = 0; ky < 12; ky++) {
        float rh2 = rhv[ky];
#pragma unroll
        for (int kx = 0; kx < 12; kx++) {
            int kk = ky * 12 + kx;
            const ulonglong2* kr = (const ulonglong2*)(ks + kk * 64 + head * 16);
            ulonglong2 k0 = kr[0], k1 = kr[1], k2v = kr[2], k3 = kr[3];
            u64 a0 = mul2(q2[0], k0.x);
            u64 a1 = mul2(q2[1], k0.y);
            a0 = fma2(q2[2], k1.x, a0);
            a1 = fma2(q2[3], k1.y, a1);
            a0 = fma2(q2[4], k2v.x, a0);
            a1 = fma2(q2[5], k2v.y, a1);
            a0 = fma2(q2[6], k3.x, a0);
            a1 = fma2(q2[7], k3.y, a1);
            float l = hadd2(a0) + hadd2(a1) + rwv[kx] + rh2;
            float wg = __expf(l);
            sum += wg;
            u64 w2 = pack2(wg, wg);
            const ulonglong2* vr = (const ulonglong2*)(vs + kk * 64 + head * 16);
#pragma unroll
            for (int i = 0; i < 4; i++) {
                ulonglong2 vv = vr[i];
                acc[2*i]   = fma2(w2, vv.x, acc[2*i]);
                acc[2*i+1] = fma2(w2, vv.y, acc[2*i+1]);
            }
        }
    }
    float invs = 1.0f / sum;
    u64 inv2 = pack2(invs, invs);
    u64* oq = (u64*)(qs + tok * 68 + head * 16);
#pragma unroll
    for (int i = 0; i < 8; i++) oq[i] = mul2(acc[i], inv2);
    __syncthreads();

#pragma unroll
    for (int i = 0; i < 4; i++) {
        int fidx = i * 256 + t;
        int tk = fidx >> 4, c4 = fidx & 15;
        int py = wy * 8 + (tk >> 3), px = wx * 8 + (tk & 7);
        float4 ov = *(const float4*)(qs + tk * 68 + 4 * c4);
        *(float4*)(g_mix + ((size_t)(b * HW + py * 256 + px)) * 64 + 4 * c4) = ov;
    }
}

// ======================= K7: final conv via tf32 mma (3x split) =======================
#define FINAL_SMEM ((128*68*2 + 64*68*2) * 4)
__global__ __launch_bounds__(256) void k_final(
    const float* __restrict__ Wout, const float* __restrict__ bout,
    float* __restrict__ out)
{
    extern __shared__ __align__(16) u32 sm[];
    u32* sAh = sm;                 // [128][68]
    u32* sAl = sAh + 128*68;
    u32* sBh = sAl + 128*68;       // [64][68]
    u32* sBl = sBh + 64*68;

    int t = threadIdx.x;
    int p0 = blockIdx.x * 128;
    int bb = p0 >> 16, ploc = p0 & (HW - 1);

#pragma unroll
    for (int i = 0; i < 8; i++) {
        int fidx = i * 256 + t;
        int px = fidx >> 4, c4 = (fidx & 15) << 2;
        int g = p0 + px;
        int p = g & (HW - 1);
        int wdw = ((p >> 11) << 5) | ((p >> 3) & 31);
        float4 v;
        if (g_ishard[(g >> 16) * NW + wdw]) {
            v = *(const float4*)(g_mix + (size_t)g * 64 + c4);
        } else {
            v = *(const float4*)(g_v + (size_t)g * 64 + c4);
            float s = g_sa[g];
            v.x *= s; v.y *= s; v.z *= s; v.w *= s;
        }
        uint4 h, l;
        tf32split(v.x, h.x, l.x); tf32split(v.y, h.y, l.y);
        tf32split(v.z, h.z, l.z); tf32split(v.w, h.w, l.w);
        *(uint4*)(sAh + px * 68 + c4) = h;
        *(uint4*)(sAl + px * 68 + c4) = l;
    }
#pragma unroll
    for (int i = 0; i < 4; i++) {
        int widx = i * 256 + t;
        int oc = widx >> 4, ic4 = (widx & 15) << 2;
        float4 v = *(const float4*)(Wout + oc * 64 + ic4);
        uint4 h, l;
        tf32split(v.x, h.x, l.x); tf32split(v.y, h.y, l.y);
        tf32split(v.z, h.z, l.z); tf32split(v.w, h.w, l.w);
        *(uint4*)(sBh + oc * 68 + ic4) = h;
        *(uint4*)(sBl + oc * 68 + ic4) = l;
    }
    __syncthreads();

    int lane = t & 31, warp = t >> 5;
    int g = lane >> 2, i4 = lane & 3;
    int mg = warp >> 1, ng = warp & 1;

    float acc[2][4][4];
#pragma unroll
    for (int mt = 0; mt < 2; mt++)
#pragma unroll
        for (int nt = 0; nt < 4; nt++)
#pragma unroll
            for (int c = 0; c < 4; c++) acc[mt][nt][c] = 0.f;

#pragma unroll
    for (int kt = 0; kt < 8; kt++) {
        u32 ah[2][4], al[2][4];
#pragma unroll
        for (int mt = 0; mt < 2; mt++) {
            int mrow = mg * 32 + mt * 16 + g;
            const u32* pA = sAh + mrow * 68 + kt * 8 + i4;
            const u32* qA = sAl + mrow * 68 + kt * 8 + i4;
            ah[mt][0] = pA[0]; ah[mt][1] = pA[8*68]; ah[mt][2] = pA[4]; ah[mt][3] = pA[8*68+4];
            al[mt][0] = qA[0]; al[mt][1] = qA[8*68]; al[mt][2] = qA[4]; al[mt][3] = qA[8*68+4];
        }
        u32 bh[4][2], bl[4][2];
#pragma unroll
        for (int nt = 0; nt < 4; nt++) {
            int ocol = ng * 32 + nt * 8 + g;
            const u32* pB = sBh + ocol * 68 + kt * 8 + i4;
            const u32* qB = sBl + ocol * 68 + kt * 8 + i4;
            bh[nt][0] = pB[0]; bh[nt][1] = pB[4];
            bl[nt][0] = qB[0]; bl[nt][1] = qB[4];
        }
#pragma unroll
        for (int mt = 0; mt < 2; mt++)
#pragma unroll
            for (int nt = 0; nt < 4; nt++) {
                mma8(acc[mt][nt], ah[mt], bh[nt]);
                mma8(acc[mt][nt], ah[mt], bl[nt]);
                mma8(acc[mt][nt], al[mt], bh[nt]);
            }
    }

    float* obase = out + (size_t)bb * 64 * HW + ploc;
#pragma unroll
    for (int nt = 0; nt < 4; nt++) {
        int oc0 = ng * 32 + nt * 8 + 2 * i4;
        float b0 = bout[oc0], b1 = bout[oc0 + 1];
#pragma unroll
        for (int mt = 0; mt < 2; mt++) {
            int pxr = mg * 32 + mt * 16 + g;
            float* po = obase + (size_t)oc0 * HW + pxr;
            po[0]      = acc[mt][nt][0] + b0;
            po[HW]     = acc[mt][nt][1] + b1;
            po[8]      = acc[mt][nt][2] + b0;
            po[HW + 8] = acc[mt][nt][3] + b1;
        }
    }
}

// ======================= launch =======================
extern "C" void kernel_launch(void* const* d_in, const int* in_sizes, int n_in,
                              void* d_out, int out_size)
{
    const float* x    = (const float*)d_in[0];
    const float* cg   = (const float*)d_in[1];
    const float* Wq   = (const float*)d_in[2];
    const float* bq   = (const float*)d_in[3];
    const float* Wk   = (const float*)d_in[4];
    const float* bk   = (const float*)d_in[5];
    const float* Wv   = (const float*)d_in[6];
    const float* bv   = (const float*)d_in[7];
    const float* Wout = (const float*)d_in[8];
    const float* bout = (const float*)d_in[9];
    const float* relh = (const float*)d_in[10];
    const float* relw = (const float*)d_in[11];
    const float* pinW = (const float*)d_in[12];
    const float* pinb = (const float*)d_in[13];
    const float* lnw  = (const float*)d_in[14];
    const float* lnb  = (const float*)d_in[15];
    const float* saW  = (const float*)d_in[16];
    const float* sab  = (const float*)d_in[17];
    const float* m1W  = (const float*)d_in[18];
    const float* m1b  = (const float*)d_in[19];
    const float* m2W  = (const float*)d_in[20];
    const float* m2b  = (const float*)d_in[21];
    float* out = (float*)d_out;

    cudaFuncSetAttribute(k_qkv,   cudaFuncAttributeMaxDynamicSharedMemorySize, QKV_SMEM);
    cudaFuncSetAttribute(k_attn,  cudaFuncAttributeMaxDynamicSharedMemorySize, ATTN_SMEM);
    cudaFuncSetAttribute(k_final, cudaFuncAttributeMaxDynamicSharedMemorySize, FINAL_SMEM);

    k_qkv  <<<NPIX / 128, 256, QKV_SMEM>>>(x, Wq, bq, Wk, bk, Wv, bv);
    k_pin  <<<NPIX / 128, 128>>>(cg, pinW, pinb, lnw, lnb);
    k_sa   <<<NPIX / 256, 256>>>(saW, sab);
    k_score<<<256, 256>>>(m1W, m1b, m2W, m2b);
    k_rank <<<BATCH, 1024>>>();
    k_attn <<<BATCH * KEEP, 256, ATTN_SMEM>>>(relh, relw);
    k_final<<<NPIX / 128, 256, FINAL_SMEM>>>(Wout, bout, out);
}

// round 6
// speedup vs baseline: 1.5644x; 1.5644x over previous
#include <cuda_runtime.h>
#include <math.h>

#define HW 65536            // 256*256
#define BATCH 2
#define NPIX (BATCH*HW)     // 131072
#define NW 1024
#define KEEP 512

typedef unsigned long long u64;
typedef unsigned int u32;

// ---------------- packed f32x2 helpers ----------------
__device__ __forceinline__ u64 fma2(u64 a, u64 b, u64 c) {
    u64 d; asm("fma.rn.f32x2 %0,%1,%2,%3;" : "=l"(d) : "l"(a), "l"(b), "l"(c)); return d;
}
__device__ __forceinline__ u64 mul2(u64 a, u64 b) {
    u64 d; asm("mul.rn.f32x2 %0,%1,%2;" : "=l"(d) : "l"(a), "l"(b)); return d;
}
__device__ __forceinline__ u64 add2(u64 a, u64 b) {
    u64 d; asm("add.rn.f32x2 %0,%1,%2;" : "=l"(d) : "l"(a), "l"(b)); return d;
}
__device__ __forceinline__ u64 pack2(float lo, float hi) {
    u64 r; asm("mov.b64 %0,{%1,%2};" : "=l"(r) : "f"(lo), "f"(hi)); return r;
}
__device__ __forceinline__ float hadd2(u64 v) {
    float lo, hi; asm("mov.b64 {%0,%1},%2;" : "=f"(lo), "=f"(hi) : "l"(v)); return lo + hi;
}
__device__ __forceinline__ float lo2(u64 v) {
    float lo, hi; asm("mov.b64 {%0,%1},%2;" : "=f"(lo), "=f"(hi) : "l"(v)); return lo;
}
__device__ __forceinline__ float hi2(u64 v) {
    float lo, hi; asm("mov.b64 {%0,%1},%2;" : "=f"(lo), "=f"(hi) : "l"(v)); return hi;
}

// ---------------- tf32 helpers ----------------
__device__ __forceinline__ void tf32split(float x, u32& h, u32& l) {
    asm("cvt.rna.tf32.f32 %0,%1;" : "=r"(h) : "f"(x));
    float r = x - __uint_as_float(h);
    asm("cvt.rna.tf32.f32 %0,%1;" : "=r"(l) : "f"(r));
}
__device__ __forceinline__ void mma8(float* d, const u32* a, const u32* b) {
    asm volatile("mma.sync.aligned.m16n8k8.row.col.f32.tf32.tf32.f32 "
        "{%0,%1,%2,%3},{%4,%5,%6,%7},{%8,%9},{%0,%1,%2,%3};"
        : "+f"(d[0]), "+f"(d[1]), "+f"(d[2]), "+f"(d[3])
        : "r"(a[0]), "r"(a[1]), "r"(a[2]), "r"(a[3]), "r"(b[0]), "r"(b[1]));
}

// ---------------- scratch ----------------
__device__ float g_q[NPIX*64];     // NHWC
__device__ float g_k[NPIX*64];
__device__ float g_v[NPIX*64];
__device__ float g_mix[NPIX*64];
__device__ float g_h1p[17*NPIX];   // planar
__device__ float g_sa[NPIX];
__device__ float g_xm[NPIX];
__device__ float g_score[BATCH*NW];
__device__ int   g_hard[BATCH*KEEP];
__device__ int   g_ishard[BATCH*NW];

// ======================= K1: qkv via tf32 mma (3x split) =======================
#define QKV_SMEM ((64*136*2 + 192*68*2) * 4)
__global__ __launch_bounds__(256) void k_qkv(
    const float* __restrict__ x,
    const float* __restrict__ Wq, const float* __restrict__ bq,
    const float* __restrict__ Wk, const float* __restrict__ bk,
    const float* __restrict__ Wv, const float* __restrict__ bv)
{
    extern __shared__ __align__(16) u32 sm[];
    u32* sAh = sm;                    // [64][136]
    u32* sAl = sAh + 64*136;
    u32* sBh = sAl + 64*136;          // [192][68]
    u32* sBl = sBh + 192*68;
    float* sC = (float*)sm;           // [128][196]

    int t = threadIdx.x;
    int p0 = blockIdx.x * 128;
    int b  = p0 >> 16, p = p0 & (HW - 1);
    const float* xb = x + (size_t)b * 64 * HW + p;

#pragma unroll
    for (int i = 0; i < 8; i++) {
        int fidx = i * 256 + t;
        int ic = fidx >> 5, px4 = (fidx & 31) << 2;
        float4 v = *(const float4*)(xb + (size_t)ic * HW + px4);
        uint4 h, l;
        tf32split(v.x, h.x, l.x); tf32split(v.y, h.y, l.y);
        tf32split(v.z, h.z, l.z); tf32split(v.w, h.w, l.w);
        *(uint4*)(sAh + ic * 136 + px4) = h;
        *(uint4*)(sAl + ic * 136 + px4) = l;
    }
#pragma unroll
    for (int i = 0; i < 12; i++) {
        int widx = i * 256 + t;
        int oc = widx >> 4, ic4 = (widx & 15) << 2;
        const float* Wm = (oc < 64) ? Wq : (oc < 128) ? Wk : Wv;
        float4 v = *(const float4*)(Wm + (oc & 63) * 64 + ic4);
        uint4 h, l;
        tf32split(v.x, h.x, l.x); tf32split(v.y, h.y, l.y);
        tf32split(v.z, h.z, l.z); tf32split(v.w, h.w, l.w);
        *(uint4*)(sBh + oc * 68 + ic4) = h;
        *(uint4*)(sBl + oc * 68 + ic4) = l;
    }
    __syncthreads();

    int lane = t & 31, warp = t >> 5;
    int g = lane >> 2, i4 = lane & 3;
    int mg = warp >> 2, ng = warp & 3;

    float acc[4][6][4];
#pragma unroll
    for (int mt = 0; mt < 4; mt++)
#pragma unroll
        for (int nt = 0; nt < 6; nt++)
#pragma unroll
            for (int c = 0; c < 4; c++) acc[mt][nt][c] = 0.f;

#pragma unroll
    for (int kt = 0; kt < 8; kt++) {
        u32 ah[4][4], al[4][4];
#pragma unroll
        for (int mt = 0; mt < 4; mt++) {
            int mrow = mg * 64 + mt * 16 + g;
            const u32* pA = sAh + (kt * 8 + i4) * 136 + mrow;
            const u32* qA = sAl + (kt * 8 + i4) * 136 + mrow;
            ah[mt][0] = pA[0]; ah[mt][1] = pA[8]; ah[mt][2] = pA[4*136]; ah[mt][3] = pA[4*136+8];
            al[mt][0] = qA[0]; al[mt][1] = qA[8]; al[mt][2] = qA[4*136]; al[mt][3] = qA[4*136+8];
        }
        u32 bh[6][2], bl[6][2];
#pragma unroll
        for (int nt = 0; nt < 6; nt++) {
            int ocol = ng * 48 + nt * 8 + g;
            const u32* pB = sBh + ocol * 68 + kt * 8 + i4;
            const u32* qB = sBl + ocol * 68 + kt * 8 + i4;
            bh[nt][0] = pB[0]; bh[nt][1] = pB[4];
            bl[nt][0] = qB[0]; bl[nt][1] = qB[4];
        }
#pragma unroll
        for (int mt = 0; mt < 4; mt++)
#pragma unroll
            for (int nt = 0; nt < 6; nt++) {
                mma8(acc[mt][nt], ah[mt], bh[nt]);
                mma8(acc[mt][nt], ah[mt], bl[nt]);
                mma8(acc[mt][nt], al[mt], bh[nt]);
            }
    }
    __syncthreads();

#pragma unroll
    for (int mt = 0; mt < 4; mt++)
#pragma unroll
        for (int nt = 0; nt < 6; nt++) {
            int row = mg * 64 + mt * 16 + g;
            int col = ng * 48 + nt * 8 + 2 * i4;
            float* c = sC + row * 196 + col;
            c[0] = acc[mt][nt][0]; c[1] = acc[mt][nt][1];
            c += 8 * 196;
            c[0] = acc[mt][nt][2]; c[1] = acc[mt][nt][3];
        }
    __syncthreads();

#pragma unroll
    for (int i = 0; i < 24; i++) {
        int fidx = i * 256 + t;
        int mat = fidx >> 11;
        int r = fidx & 2047;
        int px = r >> 4, c4 = (r & 15) << 2;
        float4 v = *(float4*)(sC + px * 196 + mat * 64 + c4);
        const float* bias = (mat == 0) ? bq : (mat == 1) ? bk : bv;
        float4 bv4 = *(const float4*)(bias + c4);
        v.x += bv4.x; v.y += bv4.y; v.z += bv4.z; v.w += bv4.w;
        float* gX = (mat == 0) ? g_q : (mat == 1) ? g_k : g_v;
        *(float4*)(gX + (size_t)(p0 + px) * 64 + c4) = v;
    }
}

// ======================= K2: pin conv + LN + lrelu + xm =======================
__global__ __launch_bounds__(128) void k_pin(
    const float* __restrict__ cg,
    const float* __restrict__ pinW, const float* __restrict__ pinb,
    const float* __restrict__ lnw,  const float* __restrict__ lnb)
{
    __shared__ float vt[128][66];
    __shared__ u64 sw2[17*34];
    __shared__ float sb[17], slw[17], slb[17];

    int t = threadIdx.x;
    int p0 = blockIdx.x * 128;

    const u64* pw64 = (const u64*)pinW;
    for (int i = t; i < 17*34; i += 128) sw2[i] = pw64[i];
    if (t < 17) { sb[t] = pinb[t]; slw[t] = lnw[t]; slb[t] = lnb[t]; }

#pragma unroll
    for (int i = 0; i < 16; i++) {
        int fidx = i * 128 + t;
        int row = fidx >> 4, c4 = fidx & 15;
        float4 v = *(const float4*)(g_v + (size_t)(p0 + row) * 64 + 4 * c4);
        vt[row][4*c4+0] = v.x; vt[row][4*c4+1] = v.y;
        vt[row][4*c4+2] = v.z; vt[row][4*c4+3] = v.w;
    }
    __syncthreads();

    int g = p0 + t;
    int b = g >> 16, p = g & (HW - 1);
    int y = p >> 8, xx = p & 255;

    u64 c2[34];
    const u64* vrow = (const u64*)&vt[t][0];
#pragma unroll
    for (int i = 0; i < 32; i++) c2[i] = vrow[i];
    c2[32] = pack2(cg[(size_t)b * 2 * HW + p], cg[(size_t)b * 2 * HW + HW + p]);
    c2[33] = pack2(-1.0f + (2.0f / 7.0f) * (float)(y & 7),
                   -1.0f + (2.0f / 7.0f) * (float)(xx & 7));

    float h[17];
    for (int oc = 0; oc < 17; oc++) {
        const u64* w = &sw2[oc * 34];
        u64 a0 = 0, a1 = 0;
#pragma unroll
        for (int i = 0; i < 34; i += 2) {
            a0 = fma2(c2[i],   w[i],   a0);
            a1 = fma2(c2[i+1], w[i+1], a1);
        }
        h[oc] = sb[oc] + hadd2(a0) + hadd2(a1);
    }
    float u = 0.f;
#pragma unroll
    for (int oc = 0; oc < 17; oc++) u += h[oc];
    u *= (1.0f / 17.0f);
    float sv = 0.f;
#pragma unroll
    for (int oc = 0; oc < 17; oc++) { float d = h[oc] - u; sv += d * d; }
    sv *= (1.0f / 17.0f);
    float inv = rsqrtf(sv + 1e-6f);

    float xs = 0.f;
#pragma unroll
    for (int oc = 0; oc < 17; oc++) {
        float tv = slw[oc] * (h[oc] - u) * inv + slb[oc];
        tv = (tv >= 0.f) ? tv : 0.1f * tv;
        g_h1p[(size_t)oc * NPIX + g] = tv;
        xs += tv;
    }
    g_xm[g] = xs * (1.0f / 17.0f);
}

// ======================= K3: 3x3 conv (17->1) + sigmoid =======================
__global__ __launch_bounds__(256) void k_sa(
    const float* __restrict__ saW, const float* __restrict__ sab)
{
    __shared__ float swt[153];
    for (int i = threadIdx.x; i < 153; i += 256) swt[i] = saW[i];
    __syncthreads();
    int g = blockIdx.x * 256 + threadIdx.x;
    int b = g >> 16, p = g & (HW - 1);
    int y = p >> 8, x = p & 255;
    float acc = sab[0];
#pragma unroll
    for (int c = 0; c < 17; c++) {
        const float* plane = g_h1p + (size_t)c * NPIX + (size_t)b * HW;
        const float* wr = &swt[c * 9];
#pragma unroll
        for (int dy = -1; dy <= 1; dy++) {
            int yy = y + dy;
            if ((unsigned)yy > 255u) continue;
#pragma unroll
            for (int dx = -1; dx <= 1; dx++) {
                int xxp = x + dx;
                if ((unsigned)xxp > 255u) continue;
                acc += plane[yy * 256 + xxp] * wr[(dy + 1) * 3 + (dx + 1)];
            }
        }
    }
    g_sa[g] = 1.0f / (1.0f + __expf(-acc));
}

// ======================= K4: window score, warp-per-window =======================
__global__ __launch_bounds__(256) void k_score(
    const float* __restrict__ m1W, const float* __restrict__ m1b,
    const float* __restrict__ m2W, const float* __restrict__ m2b)
{
    int t = threadIdx.x, lane = t & 31, warp = t >> 5;
    int gw = blockIdx.x * 8 + warp;
    int b = gw >> 10, w = gw & (NW - 1);
    int wy = w >> 5, wx = w & 31;
    int qy = lane >> 2, qx2 = (lane & 3) * 2;
    int tok = qy * 8 + qx2;

    u64 xv = *(const u64*)(g_xm + b * HW + (wy * 8 + qy) * 256 + wx * 8 + qx2);
    u64 pj[4];
#pragma unroll
    for (int j2 = 0; j2 < 4; j2++) {
        u64 w0 = *(const u64*)(m1W + (2*j2) * 64 + tok);
        u64 w1 = *(const u64*)(m1W + (2*j2+1) * 64 + tok);
        pj[j2] = pack2(hadd2(mul2(xv, w0)), hadd2(mul2(xv, w1)));
    }
#pragma unroll
    for (int s = 16; s > 0; s >>= 1) {
#pragma unroll
        for (int j2 = 0; j2 < 4; j2++)
            pj[j2] = add2(pj[j2], __shfl_xor_sync(0xffffffffu, pj[j2], s));
    }
    if (lane == 0) {
        float z[8];
#pragma unroll
        for (int j2 = 0; j2 < 4; j2++) { z[2*j2] = lo2(pj[j2]); z[2*j2+1] = hi2(pj[j2]); }
        float l0 = m2b[0], l1 = m2b[1];
#pragma unroll
        for (int j = 0; j < 8; j++) {
            float a = z[j] + m1b[j];
            a = (a >= 0.f) ? a : 0.1f * a;
            l0 += a * m2W[j]; l1 += a * m2W[8 + j];
        }
        g_score[gw] = 1.0f / (1.0f + __expf(l1 - l0));
    }
}

// ======================= K5: deterministic rank -> top-512 =======================
__global__ __launch_bounds__(1024) void k_rank()
{
    __shared__ float s[NW];
    int b = blockIdx.x;
    int i = threadIdx.x;
    s[i] = g_score[b * NW + i];
    __syncthreads();
    float si = s[i];
    int r = 0;
    for (int j = 0; j < NW; j++) {
        float sj = s[j];
        r += (sj > si) || (sj == si && j < i);
    }
    if (r < KEEP) {
        g_hard[b * KEEP + r] = i;
        g_ishard[b * NW + i] = 1;
    } else {
        g_ishard[b * NW + i] = 0;
    }
}

// ======================= K6: attention, single pass, round-4 load style =======================
#define ATTN_SMEM (144*64*4*2 + 64*68*4 + 184*8*2)
__global__ __launch_bounds__(256) void k_attn(
    const float* __restrict__ relh, const float* __restrict__ relw)
{
    extern __shared__ __align__(16) char dyn[];
    float* ks = (float*)dyn;                 // K pre-scaled by 0.25
    float* vs = ks + 144*64;
    float* qs = vs + 144*64;                 // [64][68]
    u64* srw  = (u64*)(qs + 64*68);
    u64* srh  = srw + 184;

    int t = threadIdx.x;
    int head = t >> 6, tok = t & 63;
    int b = blockIdx.x >> 9;
    int w = g_hard[blockIdx.x];
    int wy = w >> 5, wx = w & 31;

    u64 s2 = pack2(0.25f, 0.25f);
    const u64* rw64 = (const u64*)relw;
    const u64* rh64 = (const u64*)relh;
    for (int i = t; i < 184; i += 256) {
        srw[i] = mul2(rw64[i], s2);
        srh[i] = mul2(rh64[i], s2);
    }

    int y0 = wy * 8 - 2, x0 = wx * 8 - 2;
#pragma unroll
    for (int i = 0; i < 9; i++) {
        int fidx = i * 256 + t;
        int kk = fidx >> 4, c4 = fidx & 15;
        int yy = y0 + kk / 12, xxp = x0 + kk % 12;
        float4 kv = make_float4(0.f, 0.f, 0.f, 0.f), vv = kv;
        if ((unsigned)yy < 256u && (unsigned)xxp < 256u) {
            size_t base = ((size_t)(b * HW + yy * 256 + xxp)) * 64 + 4 * c4;
            kv = *(const float4*)(g_k + base);
            vv = *(const float4*)(g_v + base);
            kv.x *= 0.25f; kv.y *= 0.25f; kv.z *= 0.25f; kv.w *= 0.25f;
        }
        *(float4*)(ks + kk * 64 + 4 * c4) = kv;
        *(float4*)(vs + kk * 64 + 4 * c4) = vv;
    }
#pragma unroll
    for (int i = 0; i < 4; i++) {
        int fidx = i * 256 + t;
        int tk = fidx >> 4, c4 = fidx & 15;
        int py = wy * 8 + (tk >> 3), px = wx * 8 + (tk & 7);
        float4 qv = *(const float4*)(g_q + ((size_t)(b * HW + py * 256 + px)) * 64 + 4 * c4);
        *(float4*)(qs + tk * 68 + 4 * c4) = qv;
    }
    __syncthreads();

    u64 q2[8];
    const u64* qrow = (const u64*)(qs + tok * 68 + head * 16);
#pragma unroll
    for (int i = 0; i < 8; i++) q2[i] = qrow[i];

    int qy = tok >> 3, qx = tok & 7;

    // per-column / per-row relative bias (already scaled)
    float rwv[12], rhv[12];
#pragma unroll
    for (int k2 = 0; k2 < 12; k2++) {
        const u64* pw = &srw[(k2 - qx + 11) * 8];
        const u64* ph = &srh[(k2 - qy + 11) * 8];
        u64 a0 = 0, a1 = 0, c0 = 0, c1 = 0;
#pragma unroll
        for (int i = 0; i < 8; i += 2) {
            a0 = fma2(q2[i],   pw[i],   a0);
            a1 = fma2(q2[i+1], pw[i+1], a1);
            c0 = fma2(q2[i],   ph[i],   c0);
            c1 = fma2(q2[i+1], ph[i+1], c1);
        }
        rwv[k2] = hadd2(a0) + hadd2(a1);
        rhv[k2] = hadd2(c0) + hadd2(c1);
    }

    // single pass: exp without max subtraction (logits are small), accumulate V
    float sum = 0.f;
    u64 acc[8] = {0,0,0,0,0,0,0,0};
    for (int ky = 0; ky < 12; ky++) {
        float rh2 = rhv[ky];
#pragma unroll
        for (int kx = 0; kx < 12; kx++) {
            int kk = ky * 12 + kx;
            const u64* kr = (const u64*)(ks + kk * 64 + head * 16);
            u64 a0 = 0, a1 = 0;
#pragma unroll
            for (int i = 0; i < 8; i += 2) {
                a0 = fma2(q2[i],   kr[i],   a0);
                a1 = fma2(q2[i+1], kr[i+1], a1);
            }
            float l = hadd2(a0) + hadd2(a1) + rwv[kx] + rh2;
            float wg = __expf(l);
            sum += wg;
            u64 w2 = pack2(wg, wg);
            const u64* vr = (const u64*)(vs + kk * 64 + head * 16);
#pragma unroll
            for (int i = 0; i < 8; i++) acc[i] = fma2(w2, vr[i], acc[i]);
        }
    }
    float invs = 1.0f / sum;
    u64 inv2 = pack2(invs, invs);
    u64* oq = (u64*)(qs + tok * 68 + head * 16);
#pragma unroll
    for (int i = 0; i < 8; i++) oq[i] = mul2(acc[i], inv2);
    __syncthreads();

#pragma unroll
    for (int i = 0; i < 4; i++) {
        int fidx = i * 256 + t;
        int tk = fidx >> 4, c4 = fidx & 15;
        int py = wy * 8 + (tk >> 3), px = wx * 8 + (tk & 7);
        float4 ov = *(const float4*)(qs + tk * 68 + 4 * c4);
        *(float4*)(g_mix + ((size_t)(b * HW + py * 256 + px)) * 64 + 4 * c4) = ov;
    }
}

// ======================= K7: final conv via tf32 mma (3x split) =======================
#define FINAL_SMEM ((128*68*2 + 64*68*2) * 4)
__global__ __launch_bounds__(256) void k_final(
    const float* __restrict__ Wout, const float* __restrict__ bout,
    float* __restrict__ out)
{
    extern __shared__ __align__(16) u32 sm[];
    u32* sAh = sm;                 // [128][68]
    u32* sAl = sAh + 128*68;
    u32* sBh = sAl + 128*68;       // [64][68]
    u32* sBl = sBh + 64*68;

    int t = threadIdx.x;
    int p0 = blockIdx.x * 128;
    int bb = p0 >> 16, ploc = p0 & (HW - 1);

#pragma unroll
    for (int i = 0; i < 8; i++) {
        int fidx = i * 256 + t;
        int px = fidx >> 4, c4 = (fidx & 15) << 2;
        int g = p0 + px;
        int p = g & (HW - 1);
        int wdw = ((p >> 11) << 5) | ((p >> 3) & 31);
        float4 v;
        if (g_ishard[(g >> 16) * NW + wdw]) {
            v = *(const float4*)(g_mix + (size_t)g * 64 + c4);
        } else {
            v = *(const float4*)(g_v + (size_t)g * 64 + c4);
            float s = g_sa[g];
            v.x *= s; v.y *= s; v.z *= s; v.w *= s;
        }
        uint4 h, l;
        tf32split(v.x, h.x, l.x); tf32split(v.y, h.y, l.y);
        tf32split(v.z, h.z, l.z); tf32split(v.w, h.w, l.w);
        *(uint4*)(sAh + px * 68 + c4) = h;
        *(uint4*)(sAl + px * 68 + c4) = l;
    }
#pragma unroll
    for (int i = 0; i < 4; i++) {
        int widx = i * 256 + t;
        int oc = widx >> 4, ic4 = (widx & 15) << 2;
        float4 v = *(const float4*)(Wout + oc * 64 + ic4);
        uint4 h, l;
        tf32split(v.x, h.x, l.x); tf32split(v.y, h.y, l.y);
        tf32split(v.z, h.z, l.z); tf32split(v.w, h.w, l.w);
        *(uint4*)(sBh + oc * 68 + ic4) = h;
        *(uint4*)(sBl + oc * 68 + ic4) = l;
    }
    __syncthreads();

    int lane = t & 31, warp = t >> 5;
    int g = lane >> 2, i4 = lane & 3;
    int mg = warp >> 1, ng = warp & 1;

    float acc[2][4][4];
#pragma unroll
    for (int mt = 0; mt < 2; mt++)
#pragma unroll
        for (int nt = 0; nt < 4; nt++)
#pragma unroll
            for (int c = 0; c < 4; c++) acc[mt][nt][c] = 0.f;

#pragma unroll
    for (int kt = 0; kt < 8; kt++) {
        u32 ah[2][4], al[2][4];
#pragma unroll
        for (int mt = 0; mt < 2; mt++) {
            int mrow = mg * 32 + mt * 16 + g;
            const u32* pA = sAh + mrow * 68 + kt * 8 + i4;
            const u32* qA = sAl + mrow * 68 + kt * 8 + i4;
            ah[mt][0] = pA[0]; ah[mt][1] = pA[8*68]; ah[mt][2] = pA[4]; ah[mt][3] = pA[8*68+4];
            al[mt][0] = qA[0]; al[mt][1] = qA[8*68]; al[mt][2] = qA[4]; al[mt][3] = qA[8*68+4];
        }
        u32 bh[4][2], bl[4][2];
#pragma unroll
        for (int nt = 0; nt < 4; nt++) {
            int ocol = ng * 32 + nt * 8 + g;
            const u32* pB = sBh + ocol * 68 + kt * 8 + i4;
            const u32* qB = sBl + ocol * 68 + kt * 8 + i4;
            bh[nt][0] = pB[0]; bh[nt][1] = pB[4];
            bl[nt][0] = qB[0]; bl[nt][1] = qB[4];
        }
#pragma unroll
        for (int mt = 0; mt < 2; mt++)
#pragma unroll
            for (int nt = 0; nt < 4; nt++) {
                mma8(acc[mt][nt], ah[mt], bh[nt]);
                mma8(acc[mt][nt], ah[mt], bl[nt]);
                mma8(acc[mt][nt], al[mt], bh[nt]);
            }
    }

    float* obase = out + (size_t)bb * 64 * HW + ploc;
#pragma unroll
    for (int nt = 0; nt < 4; nt++) {
        int oc0 = ng * 32 + nt * 8 + 2 * i4;
        float b0 = bout[oc0], b1 = bout[oc0 + 1];
#pragma unroll
        for (int mt = 0; mt < 2; mt++) {
            int pxr = mg * 32 + mt * 16 + g;
            float* po = obase + (size_t)oc0 * HW + pxr;
            po[0]      = acc[mt][nt][0] + b0;
            po[HW]     = acc[mt][nt][1] + b1;
            po[8]      = acc[mt][nt][2] + b0;
            po[HW + 8] = acc[mt][nt][3] + b1;
        }
    }
}

// ======================= launch =======================
extern "C" void kernel_launch(void* const* d_in, const int* in_sizes, int n_in,
                              void* d_out, int out_size)
{
    const float* x    = (const float*)d_in[0];
    const float* cg   = (const float*)d_in[1];
    const float* Wq   = (const float*)d_in[2];
    const float* bq   = (const float*)d_in[3];
    const float* Wk   = (const float*)d_in[4];
    const float* bk   = (const float*)d_in[5];
    const float* Wv   = (const float*)d_in[6];
    const float* bv   = (const float*)d_in[7];
    const float* Wout = (const float*)d_in[8];
    const float* bout = (const float*)d_in[9];
    const float* relh = (const float*)d_in[10];
    const float* relw = (const float*)d_in[11];
    const float* pinW = (const float*)d_in[12];
    const float* pinb = (const float*)d_in[13];
    const float* lnw  = (const float*)d_in[14];
    const float* lnb  = (const float*)d_in[15];
    const float* saW  = (const float*)d_in[16];
    const float* sab  = (const float*)d_in[17];
    const float* m1W  = (const float*)d_in[18];
    const float* m1b  = (const float*)d_in[19];
    const float* m2W  = (const float*)d_in[20];
    const float* m2b  = (const float*)d_in[21];
    float* out = (float*)d_out;

    cudaFuncSetAttribute(k_qkv,   cudaFuncAttributeMaxDynamicSharedMemorySize, QKV_SMEM);
    cudaFuncSetAttribute(k_attn,  cudaFuncAttributeMaxDynamicSharedMemorySize, ATTN_SMEM);
    cudaFuncSetAttribute(k_final, cudaFuncAttributeMaxDynamicSharedMemorySize, FINAL_SMEM);

    k_qkv  <<<NPIX / 128, 256, QKV_SMEM>>>(x, Wq, bq, Wk, bk, Wv, bv);
    k_pin  <<<NPIX / 128, 128>>>(cg, pinW, pinb, lnw, lnb);
    k_sa   <<<NPIX / 256, 256>>>(saW, sab);
    k_score<<<256, 256>>>(m1W, m1b, m2W, m2b);
    k_rank <<<BATCH, 1024>>>();
    k_attn <<<BATCH * KEEP, 256, ATTN_SMEM>>>(relh, relw);
    k_final<<<NPIX / 128, 256, FINAL_SMEM>>>(Wout, bout, out);
}